// round 3
// baseline (speedup 1.0000x reference)
#include <cuda_runtime.h>
#include <cstdint>

#define BQ   2
#define NCAM 6
#define CCH  256
#define MQ   900
#define NLVL 4
#define EPSV 1e-5f

__constant__ int c_H[NLVL]  = {116, 58, 29, 15};
__constant__ int c_W[NLVL]  = {200, 100, 50, 25};
__constant__ int c_HW[NLVL] = {23200, 5800, 1450, 375};

#define NENT (NCAM * NLVL)

__device__ __forceinline__ float sel4(float4 q, int s) {
    return (s == 0) ? q.x : (s == 1) ? q.y : (s == 2) ? q.z : q.w;
}

__global__ __launch_bounds__(CCH, 8)
void FeatureSampler_kernel(const float* __restrict__ f0,
                           const float* __restrict__ f1,
                           const float* __restrict__ f2,
                           const float* __restrict__ f3,
                           const float* __restrict__ refpts,
                           const float* __restrict__ l2i,
                           float* __restrict__ out)
{
    const int bm = blockIdx.x;
    const int b  = bm / MQ;
    const int c  = threadIdx.x;

    __shared__ const float* s_base[NENT];
    __shared__ int   s_HW[NENT];
    __shared__ int   s_idx[NENT][4];
    __shared__ float s_w[NENT][4];
    __shared__ int   s_act[NENT];   // 0 none, 1 float2 pair, 2 float4-window, 3 scalar
    __shared__ float s_valid[NCAM];
    __shared__ int   s_list[NENT];
    __shared__ int   s_ne;

    // ---- Phase 1: threads 0..23 build per-(camera,level) sampling entries ----
    if (threadIdx.x < NENT) {
        const int t   = threadIdx.x;
        const int n   = t >> 2;
        const int lvl = t & 3;

        const float* rp = refpts + (size_t)bm * 3;
        float rx = rp[0] * 122.4f - 61.2f;
        float ry = rp[1] * 122.4f - 61.2f;
        float rz = rp[2] * 20.0f  - 10.0f;

        const float* Mt = l2i + (size_t)(b * NCAM + n) * 16;
        float cx = Mt[0]*rx + Mt[1]*ry + Mt[2] *rz + Mt[3];
        float cy = Mt[4]*rx + Mt[5]*ry + Mt[6] *rz + Mt[7];
        float cz = Mt[8]*rx + Mt[9]*ry + Mt[10]*rz + Mt[11];

        bool vcam = (cz > EPSV);
        if (lvl == 0) s_valid[n] = vcam ? 1.0f : 0.0f;

        float inv = 1.0f / (cz + EPSV);
        float x = cx * inv - 0.5f;   // grid_sample denorm cancels across levels
        float y = cy * inv - 0.5f;

        const int W  = c_W[lvl];
        const int H  = c_H[lvl];
        const int HW = c_HW[lvl];

        int active = 0;
        if (vcam && (x > -1.0f) && (x < (float)W) && (y > -1.0f) && (y < (float)H)) {
            float x0f = floorf(x), y0f = floorf(y);
            float wx1 = x - x0f, wx0 = 1.0f - wx1;
            float wy1 = y - y0f, wy0 = 1.0f - wy1;

            bool vx0 = (x0f >= 0.0f)        && (x0f <= (float)(W - 1));
            bool vx1 = (x0f + 1.0f >= 0.0f) && (x0f + 1.0f <= (float)(W - 1));
            bool vy0 = (y0f >= 0.0f)        && (y0f <= (float)(H - 1));
            bool vy1 = (y0f + 1.0f >= 0.0f) && (y0f + 1.0f <= (float)(H - 1));

            int xi0 = (int)fminf(fmaxf(x0f,        0.0f), (float)(W - 1));
            int xi1 = (int)fminf(fmaxf(x0f + 1.0f, 0.0f), (float)(W - 1));
            int yi0 = (int)fminf(fmaxf(y0f,        0.0f), (float)(H - 1));
            int yi1 = (int)fminf(fmaxf(y0f + 1.0f, 0.0f), (float)(H - 1));

            float w00 = (vx0 && vy0) ? (wx0 * wy0) : 0.0f;
            float w01 = (vx1 && vy0) ? (wx1 * wy0) : 0.0f;
            float w10 = (vx0 && vy1) ? (wx0 * wy1) : 0.0f;
            float w11 = (vx1 && vy1) ? (wx1 * wy1) : 0.0f;

            if ((w00 != 0.0f) || (w01 != 0.0f) || (w10 != 0.0f) || (w11 != 0.0f)) {
                int i0 = yi0 * W + xi0;
                int i2 = yi1 * W + xi0;
                bool interior = (xi1 == xi0 + 1);
                // mode 1: lvl<3 (HW,W even -> warp-uniform 8B alignment), i0 even,
                //         float2 span [xi0, xi0+1] fully inside row
                bool m1 = interior && (lvl < 3) && ((i0 & 1) == 0);
                // mode 2: per-lane float4 window; guard window [i-3, i+3] inside plane
                bool m2 = interior && (i0 >= 3) && (i2 + 3 < HW);
                active = m1 ? 1 : (m2 ? 2 : 3);

                const float* fl = (lvl == 0) ? f0 : (lvl == 1) ? f1 : (lvl == 2) ? f2 : f3;
                s_base[t]   = fl + (size_t)(b * NCAM + n) * CCH * HW;
                s_HW[t]     = HW;
                s_idx[t][0] = i0;
                s_idx[t][1] = yi0 * W + xi1;
                s_idx[t][2] = i2;
                s_idx[t][3] = yi1 * W + xi1;
                s_w[t][0] = w00;  s_w[t][1] = w01;
                s_w[t][2] = w10;  s_w[t][3] = w11;
            }
        }
        s_act[t] = active;
    }
    __syncthreads();

    if (threadIdx.x == 0) {
        int ne = 0;
        #pragma unroll
        for (int e = 0; e < NENT; e++)
            if (s_act[e]) s_list[ne++] = e;
        s_ne = ne;
    }
    __syncthreads();

    const float cnt = s_valid[0] + s_valid[1] + s_valid[2] +
                      s_valid[3] + s_valid[4] + s_valid[5];
    const int ne = s_ne;

    // ---- Phase 2: gather ----
    float acc = 0.0f;
    for (int k = 0; k < ne; k++) {
        const int e = s_list[k];
        const int mode = s_act[e];
        const float* p = s_base[e] + (size_t)c * s_HW[e];
        const float w0 = s_w[e][0], w1 = s_w[e][1];
        const float w2 = s_w[e][2], w3 = s_w[e][3];
        const int i0 = s_idx[e][0];
        const int i2 = s_idx[e][2];

        if (mode == 1) {
            // warp-uniform 8B-aligned: one LDG.64 per row covers both x-corners
            float2 q0 = __ldg((const float2*)(p + i0));
            float2 q1 = __ldg((const float2*)(p + i2));
            acc += w0*q0.x + w1*q0.y + w2*q1.x + w3*q1.y;
        } else if (mode == 2) {
            // per-lane aligned float4 window + predicated straddle load
            uintptr_t a0 = (uintptr_t)(p + i0);
            uintptr_t a1 = (uintptr_t)(p + i2);
            int sel0 = (int)((a0 >> 2) & 3);
            int sel1 = (int)((a1 >> 2) & 3);
            float4 q0 = __ldg((const float4*)(a0 & ~(uintptr_t)15));
            float4 q1 = __ldg((const float4*)(a1 & ~(uintptr_t)15));
            float v00 = sel4(q0, sel0);
            float v10 = sel4(q1, sel1);
            float v01 = (sel0 < 3) ? sel4(q0, sel0 + 1) : __ldg(p + i0 + 1);
            float v11 = (sel1 < 3) ? sel4(q1, sel1 + 1) : __ldg(p + i2 + 1);
            acc += w0*v00 + w1*v01 + w2*v10 + w3*v11;
        } else {
            float v00 = __ldg(p + i0);
            float v01 = __ldg(p + s_idx[e][1]);
            float v10 = __ldg(p + i2);
            float v11 = __ldg(p + s_idx[e][3]);
            acc += w0*v00 + w1*v01 + w2*v10 + w3*v11;
        }
    }

    out[(size_t)bm * CCH + c] = acc * 0.25f / (cnt + EPSV);
}

extern "C" void kernel_launch(void* const* d_in, const int* in_sizes, int n_in,
                              void* d_out, int out_size)
{
    const float* f0  = (const float*)d_in[0];
    const float* f1  = (const float*)d_in[1];
    const float* f2  = (const float*)d_in[2];
    const float* f3  = (const float*)d_in[3];
    const float* rp  = (const float*)d_in[4];
    const float* l2i = (const float*)d_in[5];
    float* out = (float*)d_out;

    dim3 grid(BQ * MQ);
    dim3 block(CCH);
    FeatureSampler_kernel<<<grid, block>>>(f0, f1, f2, f3, rp, l2i, out);
}